// round 9
// baseline (speedup 1.0000x reference)
#include <cuda_runtime.h>
#include <cuda_fp16.h>
#include <cstdint>

#define HW 128
#define KSZ 255
#define NTHR 256
#define NPC 2            // images per CTA

// smem byte offsets
#define OFF_WHP 0        // 254 fp16-pairs of wh
#define OFF_WWP 1024     // 254 fp16-pairs of ww
#define OFF_SW0 2048     // staged wh row (fp32, 1020B)
#define OFF_SW1 3072     // staged ww row
#define OFF_X   4096     // X^T / Y fp16 plane (32KB)
#define OFF_STG 36864    // raw X staging (fp32, 64KB)
#define SMEM_TOTAL 102400  // 100KB -> 2 CTAs/SM

// K-major fp16 plane: 128 rows x 256B; 16B chunks XOR-swizzled by row&7.
__device__ __forceinline__ uint32_t off_rk(int r, int k) {
    return (uint32_t)(r * 256 + ((((k >> 3) ^ (r & 7)) << 4) | ((k & 7) << 1)));
}

__device__ __forceinline__ uint32_t s2u(const void* p) {
    uint32_t a;
    asm("{ .reg .u64 t; cvta.to.shared.u64 t, %1; cvt.u32.u64 %0, t; }" : "=r"(a) : "l"(p));
    return a;
}

__device__ __forceinline__ void ldsm4(uint32_t* r, uint32_t a) {
    asm volatile("ldmatrix.sync.aligned.m8n8.x4.shared.b16 {%0,%1,%2,%3},[%4];"
                 : "=r"(r[0]), "=r"(r[1]), "=r"(r[2]), "=r"(r[3]) : "r"(a));
}

__device__ __forceinline__ void mma_f16(float* d, uint32_t a0, uint32_t a1, uint32_t a2,
                                        uint32_t a3, uint32_t b0, uint32_t b1) {
    asm volatile(
        "mma.sync.aligned.m16n8k16.row.col.f32.f16.f16.f32 "
        "{%0,%1,%2,%3},{%4,%5,%6,%7},{%8,%9},{%0,%1,%2,%3};"
        : "+f"(d[0]), "+f"(d[1]), "+f"(d[2]), "+f"(d[3])
        : "r"(a0), "r"(a1), "r"(a2), "r"(a3), "r"(b0), "r"(b1));
}

__device__ __forceinline__ uint32_t pack2(float a, float b) {
    __half2 h = __floats2half2_rn(a, b);
    return *(uint32_t*)&h;
}

__device__ __forceinline__ uint32_t lds32(uint32_t addr) {
    uint32_t v;
    asm volatile("ld.shared.b32 %0, [%1];" : "=r"(v) : "r"(addr));
    return v;
}

__device__ __forceinline__ void cpa16(uint32_t dst, const void* src) {
    asm volatile("cp.async.cg.shared.global [%0], [%1], 16;" :: "r"(dst), "l"(src));
}
__device__ __forceinline__ void cpa4(uint32_t dst, const void* src) {
    asm volatile("cp.async.ca.shared.global [%0], [%1], 4;" :: "r"(dst), "l"(src));
}
__device__ __forceinline__ void cp_commit() {
    asm volatile("cp.async.commit_group;" ::: "memory");
}
__device__ __forceinline__ void cp_wait0() {
    asm volatile("cp.async.wait_group 0;" ::: "memory");
}

// Prefetch raw X image + both weight rows into staging (cp.async, background).
__device__ __forceinline__ void prefetch_img(uint32_t sb, const float* x,
                                             const float* wh, const float* ww,
                                             int img, int t) {
    int c = img & 255;
    const char* src = (const char*)(x + ((size_t)img << 14));
    uint32_t dst = sb + OFF_STG;
#pragma unroll
    for (int r = 0; r < 16; r++) {
        int g = t + NTHR * r;               // 16B chunk index, 4096 total
        cpa16(dst + 16u * (uint32_t)g, src + 16 * (size_t)g);
    }
    if (t < KSZ) {
        cpa4(sb + OFF_SW0 + 4u * t, wh + c * KSZ + t);
        cpa4(sb + OFF_SW1 + 4u * t, ww + c * KSZ + t);
    }
    cp_commit();
}

extern "C" __global__ void __launch_bounds__(NTHR, 2)
conv_mma_kernel(const float* __restrict__ x,
                const float* __restrict__ wh, const float* __restrict__ bh,
                const float* __restrict__ ww, const float* __restrict__ bw,
                float* __restrict__ out) {
    extern __shared__ __align__(1024) char smem[];
    uint32_t sb = s2u(smem);
    int t = threadIdx.x, lane = t & 31, wid = t >> 5;
    int img0 = blockIdx.x * NPC;

    prefetch_img(sb, x, wh, ww, img0, t);

    int liA = lane & 15, khA = lane >> 4;
    int nB = lane & 7, khB = (lane & 15) >> 3, tB = lane >> 4;

#pragma unroll 1
    for (int k = 0; k < NPC; k++) {
        int img = img0 + k, c = img & 255;
        size_t base = (size_t)img << 14;
        float bhc = bh[c], bwc = bw[c];    // early LDG, consumed at acc init

        cp_wait0();
        __syncthreads();                   // staging visible; plane free for reuse

        // Weight pair tables from staged fp32 rows (LDS).
        if (t < KSZ - 1) {
            const float* s0 = (const float*)(smem + OFF_SW0);
            const float* s1 = (const float*)(smem + OFF_SW1);
            *(uint32_t*)(smem + OFF_WHP + 4 * t) = pack2(s0[t], s0[t + 1]);
            *(uint32_t*)(smem + OFF_WWP + 4 * t) = pack2(s1[t], s1[t + 1]);
        }

        // Convert staged X -> transposed fp16 plane: plane[w][i] = f16(X[i][w]).
        {
            int w = t & 127, ihalf = t >> 7;
            const float* sx = (const float*)(smem + OFF_STG);
#pragma unroll
            for (int blk = 0; blk < 8; blk++) {
                int i0 = ihalf * 64 + blk * 8;
                uint32_t q[4];
#pragma unroll
                for (int j = 0; j < 4; j++)
                    q[j] = pack2(sx[(i0 + 2 * j) * HW + w], sx[(i0 + 2 * j + 1) * HW + w]);
                *(uint4*)(smem + OFF_X + off_rk(w, i0)) = *(uint4*)q;
            }
        }
        __syncthreads();                   // staging consumed; plane + tables ready

        if (k + 1 < NPC) prefetch_img(sb, x, wh, ww, img + 1, t);  // background

        // ---- Stage 1: Y[h][w] = Toep(wh) @ X.  Warp grid 2(m) x 4(n). ----
        int mwb = (wid >> 2) * 64, nwb = (wid & 3) * 32;
        float d1[4][4][4];
#pragma unroll
        for (int tm = 0; tm < 4; tm++)
#pragma unroll
            for (int tn = 0; tn < 4; tn++)
#pragma unroll
                for (int q = 0; q < 4; q++) d1[tm][tn][q] = bhc;

        {
            uint32_t pw = sb + OFF_WHP;
            int ibase = 127 + 2 * (lane & 3) - (mwb + (lane >> 2));
            uint32_t W[9];
#pragma unroll
            for (int m = 2; m < 9; m++) W[m] = lds32(pw + 4u * (uint32_t)(ibase + 8 * (1 - m)));

            uint32_t bRow = (uint32_t)(nwb + 8 * tB + nB) * 256;
#pragma unroll
            for (int kk = 0; kk < 8; kk++) {
                if (kk) {
#pragma unroll
                    for (int m = 8; m >= 2; m--) W[m] = W[m - 2];
                }
                W[1] = lds32(pw + 4u * (uint32_t)(ibase + 8 * (2 * kk)));
                W[0] = lds32(pw + 4u * (uint32_t)(ibase + 8 * (2 * kk + 1)));

                uint32_t bx = (uint32_t)(((2 * kk + khB) ^ nB) << 4);
                uint32_t bb[2][4];
#pragma unroll
                for (int g = 0; g < 2; g++) ldsm4(bb[g], sb + OFF_X + bRow + g * 4096 + bx);
#pragma unroll
                for (int tm = 0; tm < 4; tm++) {
                    uint32_t a0 = W[1 + 2 * tm], a1 = W[2 + 2 * tm], a2 = W[2 * tm];
#pragma unroll
                    for (int tn = 0; tn < 4; tn++)
                        mma_f16(d1[tm][tn], a0, a1, a2, a0,
                                bb[tn >> 1][(tn & 1) * 2], bb[tn >> 1][(tn & 1) * 2 + 1]);
                }
            }
        }
        __syncthreads();

        // Mid-epilogue: Y -> fp16 plane, k-major [h][w]
        {
            int ro = lane >> 2, co = (lane & 3) * 2;
#pragma unroll
            for (int tm = 0; tm < 4; tm++)
#pragma unroll
                for (int tn = 0; tn < 4; tn++) {
                    int r0 = mwb + tm * 16 + ro;
                    int c0 = nwb + tn * 8 + co;
                    *(uint32_t*)(smem + OFF_X + off_rk(r0, c0)) =
                        pack2(d1[tm][tn][0], d1[tm][tn][1]);
                    *(uint32_t*)(smem + OFF_X + off_rk(r0 + 8, c0)) =
                        pack2(d1[tm][tn][2], d1[tm][tn][3]);
                }
        }
        __syncthreads();

        // ---- Stage 2: Z[h][w'] = Y @ Toep(ww)^T.  Warp grid 4(m) x 2(n). ----
        int mwb2 = (wid & 3) * 32, nwb2 = (wid >> 2) * 64;
        float d2[2][8][4];
#pragma unroll
        for (int tm = 0; tm < 2; tm++)
#pragma unroll
            for (int tn = 0; tn < 8; tn++)
#pragma unroll
                for (int q = 0; q < 4; q++) d2[tm][tn][q] = bwc;

        {
            uint32_t pw = sb + OFF_WWP;
            int ibase = 127 + 2 * (lane & 3) - (nwb2 + (lane >> 2));
            uint32_t W[9];
#pragma unroll
            for (int m = 2; m < 9; m++) W[m] = lds32(pw + 4u * (uint32_t)(ibase + 8 * (1 - m)));

            uint32_t aRow = (uint32_t)(mwb2 + liA) * 256;
#pragma unroll
            for (int kk = 0; kk < 8; kk++) {
                if (kk) {
#pragma unroll
                    for (int m = 8; m >= 2; m--) W[m] = W[m - 2];
                }
                W[1] = lds32(pw + 4u * (uint32_t)(ibase + 8 * (2 * kk)));
                W[0] = lds32(pw + 4u * (uint32_t)(ibase + 8 * (2 * kk + 1)));

                uint32_t ax = (uint32_t)(((2 * kk + khA) ^ (liA & 7)) << 4);
                uint32_t af[2][4];
#pragma unroll
                for (int tm = 0; tm < 2; tm++)
                    ldsm4(af[tm], sb + OFF_X + aRow + tm * 4096 + ax);
#pragma unroll
                for (int tm = 0; tm < 2; tm++)
#pragma unroll
                    for (int tn = 0; tn < 8; tn++)
                        mma_f16(d2[tm][tn], af[tm][0], af[tm][1], af[tm][2], af[tm][3],
                                W[1 + tn], W[tn]);
            }
        }

        // Final epilogue: Z -> global (float2 stores, fire-and-forget)
        {
            int ro = lane >> 2, co = (lane & 3) * 2;
#pragma unroll
            for (int tm = 0; tm < 2; tm++)
#pragma unroll
                for (int tn = 0; tn < 8; tn++) {
                    int r0 = mwb2 + tm * 16 + ro;
                    int c0 = nwb2 + tn * 8 + co;
                    float2 v0 = make_float2(d2[tm][tn][0], d2[tm][tn][1]);
                    float2 v1 = make_float2(d2[tm][tn][2], d2[tm][tn][3]);
                    *(float2*)(out + base + (size_t)r0 * HW + c0) = v0;
                    *(float2*)(out + base + (size_t)(r0 + 8) * HW + c0) = v1;
                }
        }
    }
}

extern "C" void kernel_launch(void* const* d_in, const int* in_sizes, int n_in,
                              void* d_out, int out_size) {
    const float* x  = (const float*)d_in[0];
    const float* wh = (const float*)d_in[1];
    const float* bh = (const float*)d_in[2];
    const float* ww = (const float*)d_in[3];
    const float* bw = (const float*)d_in[4];
    float* out = (float*)d_out;

    int nimg = in_sizes[0] >> 14;
    int grid = (nimg + NPC - 1) / NPC;
    cudaFuncSetAttribute(conv_mma_kernel,
                         cudaFuncAttributeMaxDynamicSharedMemorySize, SMEM_TOTAL);
    conv_mma_kernel<<<grid, NTHR, SMEM_TOTAL>>>(x, wh, bh, ww, bw, out);
}